// round 11
// baseline (speedup 1.0000x reference)
#include <cuda_runtime.h>
#include <math.h>

#define B_   4096
#define D_   1024
#define F_   24576
#define K1   32      /* TOPK */
#define K2_  256     /* DEAD_TOPK */
#define DEAD_CUT 100000
#define NTH  512     /* threads in row kernel */

// ---------------------------------------------------------------------------
// Scratch (device globals: no cudaMalloc allowed)
// ---------------------------------------------------------------------------
__device__ float  g_project[(size_t)B_ * (size_t)F_];   // 402 MB
__device__ double g_sum;
__device__ double g_sumsq;

__global__ void zero_stats_kernel() {
    g_sum = 0.0;
    g_sumsq = 0.0;
}

// ---------------------------------------------------------------------------
// packed f32x2 helpers (SASS FFMA2 — only reachable via PTX fma.rn.f32x2)
// Each half is an IEEE fp32 FMA: bit-identical math to scalar FFMA.
// ---------------------------------------------------------------------------
__device__ __forceinline__ void fma2(unsigned long long& d,
                                     unsigned long long a,
                                     unsigned long long b) {
    asm("fma.rn.f32x2 %0, %1, %2, %0;" : "+l"(d) : "l"(a), "l"(b));
}
__device__ __forceinline__ void add2(unsigned long long& d,
                                     unsigned long long a) {
    asm("add.rn.f32x2 %0, %0, %1;" : "+l"(d) : "l"(a));
}
__device__ __forceinline__ unsigned long long dup2(float x) {
    unsigned u = __float_as_uint(x);
    return ((unsigned long long)u << 32) | (unsigned long long)u;
}
__device__ __forceinline__ void unpack2(unsigned long long v, float& lo, float& hi) {
    asm("mov.b64 {%0, %1}, %2;" : "=f"(lo), "=f"(hi) : "l"(v));
}

// ---------------------------------------------------------------------------
// SGEMM: project[b,f] = sum_d (embed[b,d]-bias[d]) * W[f,d]
// 128x128 tile, BK=16, 256 threads, 8x8 micro-tile, double buffered.
// Mainloop uses packed fma.rn.f32x2 (FFMA2): accumulators paired along M
// (rows 2p / 2p+1 in lo/hi), B stored DUPLICATED in smem so one LDS.128
// yields two broadcast pairs. Per-element fp32 op sequence is identical to
// the scalar version (two-level tile accumulation kept) -> bit-exact.
// Also accumulates global sum / sumsq of project for std().
// ---------------------------------------------------------------------------
#define BM 128
#define BN 128
#define BK 16

__global__ __launch_bounds__(256, 1)
void gemm_kernel(const float* __restrict__ embed,
                 const float* __restrict__ bias,
                 const float* __restrict__ W)
{
    __shared__ __align__(16) float As[2][BK][BM];            // 16 KB
    __shared__ __align__(16) float Bsd[2][BK][2 * BN];       // 32 KB (duplicated)

    const int tid  = threadIdx.x;
    const int row0 = blockIdx.y * BM;   // batch rows
    const int col0 = blockIdx.x * BN;   // feature cols

    // loader mapping: each thread loads 2 float4 for A and 2 for B per stage
    const int ar0 = tid >> 2;                 // rows 0..63
    const int ar1 = (tid + 256) >> 2;         // rows 64..127
    const int aq  = tid & 3;                  // which float4 of the 16-wide k slab

    const float* Ap0 = embed + (size_t)(row0 + ar0) * D_ + aq * 4;
    const float* Ap1 = embed + (size_t)(row0 + ar1) * D_ + aq * 4;
    const float* Bp0 = W     + (size_t)(col0 + ar0) * D_ + aq * 4;
    const float* Bp1 = W     + (size_t)(col0 + ar1) * D_ + aq * 4;

    // paired accumulators: acc2[p][j] holds rows (2p, 2p+1) of column j
    unsigned long long acc2[4][8];
#pragma unroll
    for (int p = 0; p < 4; p++)
#pragma unroll
        for (int j = 0; j < 8; j++) acc2[p][j] = 0ull;

    float4 a0, a1, b0, b1, bb;

    // preload tile 0
    a0 = *(const float4*)(Ap0);
    a1 = *(const float4*)(Ap1);
    b0 = *(const float4*)(Bp0);
    b1 = *(const float4*)(Bp1);
    bb = *(const float4*)(bias + aq * 4);

    int buf = 0;
    {
        const int kc = aq * 4;
        As[0][kc+0][ar0] = a0.x - bb.x;  As[0][kc+1][ar0] = a0.y - bb.y;
        As[0][kc+2][ar0] = a0.z - bb.z;  As[0][kc+3][ar0] = a0.w - bb.w;
        As[0][kc+0][ar1] = a1.x - bb.x;  As[0][kc+1][ar1] = a1.y - bb.y;
        As[0][kc+2][ar1] = a1.z - bb.z;  As[0][kc+3][ar1] = a1.w - bb.w;
        *(unsigned long long*)&Bsd[0][kc+0][2*ar0] = dup2(b0.x);
        *(unsigned long long*)&Bsd[0][kc+1][2*ar0] = dup2(b0.y);
        *(unsigned long long*)&Bsd[0][kc+2][2*ar0] = dup2(b0.z);
        *(unsigned long long*)&Bsd[0][kc+3][2*ar0] = dup2(b0.w);
        *(unsigned long long*)&Bsd[0][kc+0][2*ar1] = dup2(b1.x);
        *(unsigned long long*)&Bsd[0][kc+1][2*ar1] = dup2(b1.y);
        *(unsigned long long*)&Bsd[0][kc+2][2*ar1] = dup2(b1.z);
        *(unsigned long long*)&Bsd[0][kc+3][2*ar1] = dup2(b1.w);
    }
    __syncthreads();

    const int ty = tid >> 4;   // 0..15
    const int tx = tid & 15;   // 0..15
    const int NT = D_ / BK;    // 64

    for (int t = 0; t < NT; t++) {
        if (t + 1 < NT) {
            const int k0 = (t + 1) * BK;
            a0 = *(const float4*)(Ap0 + k0);
            a1 = *(const float4*)(Ap1 + k0);
            b0 = *(const float4*)(Bp0 + k0);
            b1 = *(const float4*)(Bp1 + k0);
            bb = *(const float4*)(bias + k0 + aq * 4);
        }
        // per-tile partial sums (fresh registers -> short rounding chains)
        unsigned long long ts2[4][8];
#pragma unroll
        for (int p = 0; p < 4; p++)
#pragma unroll
            for (int j = 0; j < 8; j++) ts2[p][j] = 0ull;

#pragma unroll
        for (int kk = 0; kk < BK; kk++) {
            // A pairs: (af[2p], af[2p+1]) straight from LDS.128
            ulonglong2 pa0 = *(const ulonglong2*)&As[buf][kk][ty * 8];
            ulonglong2 pa1 = *(const ulonglong2*)&As[buf][kk][ty * 8 + 4];
            unsigned long long a2[4] = { pa0.x, pa0.y, pa1.x, pa1.y };
            // B broadcast pairs: (bf[j], bf[j]) from duplicated smem
            ulonglong2 q0 = *(const ulonglong2*)&Bsd[buf][kk][tx * 16];
            ulonglong2 q1 = *(const ulonglong2*)&Bsd[buf][kk][tx * 16 + 4];
            ulonglong2 q2 = *(const ulonglong2*)&Bsd[buf][kk][tx * 16 + 8];
            ulonglong2 q3 = *(const ulonglong2*)&Bsd[buf][kk][tx * 16 + 12];
            unsigned long long b2[8] = { q0.x, q0.y, q1.x, q1.y,
                                         q2.x, q2.y, q3.x, q3.y };
#pragma unroll
            for (int p = 0; p < 4; p++)
#pragma unroll
                for (int j = 0; j < 8; j++)
                    fma2(ts2[p][j], a2[p], b2[j]);
        }
#pragma unroll
        for (int p = 0; p < 4; p++)
#pragma unroll
            for (int j = 0; j < 8; j++)
                add2(acc2[p][j], ts2[p][j]);

        if (t + 1 < NT) {
            const int nb = buf ^ 1;
            const int kc = aq * 4;
            As[nb][kc+0][ar0] = a0.x - bb.x;  As[nb][kc+1][ar0] = a0.y - bb.y;
            As[nb][kc+2][ar0] = a0.z - bb.z;  As[nb][kc+3][ar0] = a0.w - bb.w;
            As[nb][kc+0][ar1] = a1.x - bb.x;  As[nb][kc+1][ar1] = a1.y - bb.y;
            As[nb][kc+2][ar1] = a1.z - bb.z;  As[nb][kc+3][ar1] = a1.w - bb.w;
            *(unsigned long long*)&Bsd[nb][kc+0][2*ar0] = dup2(b0.x);
            *(unsigned long long*)&Bsd[nb][kc+1][2*ar0] = dup2(b0.y);
            *(unsigned long long*)&Bsd[nb][kc+2][2*ar0] = dup2(b0.z);
            *(unsigned long long*)&Bsd[nb][kc+3][2*ar0] = dup2(b0.w);
            *(unsigned long long*)&Bsd[nb][kc+0][2*ar1] = dup2(b1.x);
            *(unsigned long long*)&Bsd[nb][kc+1][2*ar1] = dup2(b1.y);
            *(unsigned long long*)&Bsd[nb][kc+2][2*ar1] = dup2(b1.z);
            *(unsigned long long*)&Bsd[nb][kc+3][2*ar1] = dup2(b1.w);
            __syncthreads();
            buf = nb;
        }
    }

    // unpack pairs back to scalar accumulators (lo = row 2p, hi = row 2p+1)
    float acc[8][8];
#pragma unroll
    for (int p = 0; p < 4; p++)
#pragma unroll
        for (int j = 0; j < 8; j++)
            unpack2(acc2[p][j], acc[2*p][j], acc[2*p+1][j]);

    // write C + accumulate stats (identical order to scalar version)
    float s = 0.0f, ss = 0.0f;
#pragma unroll
    for (int i = 0; i < 8; i++) {
        const size_t base = (size_t)(row0 + ty * 8 + i) * F_ + (col0 + tx * 8);
        float4 c0 = make_float4(acc[i][0], acc[i][1], acc[i][2], acc[i][3]);
        float4 c1 = make_float4(acc[i][4], acc[i][5], acc[i][6], acc[i][7]);
        *(float4*)&g_project[base]     = c0;
        *(float4*)&g_project[base + 4] = c1;
#pragma unroll
        for (int j = 0; j < 8; j++) { float v = acc[i][j]; s += v; ss += v * v; }
    }
#pragma unroll
    for (int o = 16; o > 0; o >>= 1) {
        s  += __shfl_down_sync(0xffffffffu, s,  o);
        ss += __shfl_down_sync(0xffffffffu, ss, o);
    }
    __shared__ double wsum[8], wss[8];
    const int w = tid >> 5, l = tid & 31;
    if (l == 0) { wsum[w] = (double)s; wss[w] = (double)ss; }
    __syncthreads();
    if (tid == 0) {
        double S = 0.0, SS = 0.0;
        for (int i = 0; i < 8; i++) { S += wsum[i]; SS += wss[i]; }
        atomicAdd(&g_sum, S);
        atomicAdd(&g_sumsq, SS);
    }
}

// ---------------------------------------------------------------------------
// Per-row top-k (exact radix select on monotone float keys) + reconstruction
// ---------------------------------------------------------------------------
__device__ __forceinline__ unsigned fkey(float v) {
    unsigned u = __float_as_uint(v);
    return (u & 0x80000000u) ? ~u : (u | 0x80000000u);
}

struct SelShared { int T; int nsel; int neq; };

__device__ void suffix_scan(unsigned* h, int NB) {
    const int tid = threadIdx.x;
    for (int off = 1; off < NB; off <<= 1) {
        unsigned v[8];
        int c = 0;
        for (int idx = tid; idx < NB; idx += NTH) {
            const int srcIdx = idx + off;
            v[c++] = (srcIdx < NB) ? h[srcIdx] : 0u;
        }
        __syncthreads();
        c = 0;
        for (int idx = tid; idx < NB; idx += NTH) h[idx] += v[c++];
        __syncthreads();
    }
}

__device__ int find_T(unsigned* h, int NB, unsigned K, int* sT) {
    const int tid = threadIdx.x;
    for (int idx = tid; idx < NB; idx += NTH)
        if (h[idx] >= K && (idx == NB - 1 || h[idx + 1] < K)) *sT = idx;
    __syncthreads();
    return *sT;
}

// exact top-K of keys sk[0..F_) -> indices in selIdx[0..K)
__device__ void select_topk(const unsigned* sk, unsigned* hist,
                            int* selIdx, int* eqIdx, int K, SelShared* sh)
{
    const int tid = threadIdx.x;
    const unsigned Ku = (unsigned)K;

    // round 1: key bits [31:20]
    for (int i = tid; i < 4096; i += NTH) hist[i] = 0u;
    __syncthreads();
    for (int i = tid; i < F_; i += NTH) atomicAdd(&hist[sk[i] >> 20], 1u);
    __syncthreads();
    suffix_scan(hist, 4096);
    const int T1 = find_T(hist, 4096, Ku, &sh->T);
    const unsigned nA1 = (T1 < 4095) ? hist[T1 + 1] : 0u;
    unsigned Kr = Ku - nA1;
    __syncthreads();

    // round 2: bits [19:8], restricted to top12 == T1
    for (int i = tid; i < 4096; i += NTH) hist[i] = 0u;
    __syncthreads();
    for (int i = tid; i < F_; i += NTH) {
        const unsigned k = sk[i];
        if ((int)(k >> 20) == T1) atomicAdd(&hist[(k >> 8) & 0xFFFu], 1u);
    }
    __syncthreads();
    suffix_scan(hist, 4096);
    const int T2 = find_T(hist, 4096, Kr, &sh->T);
    const unsigned nA2 = (T2 < 4095) ? hist[T2 + 1] : 0u;
    Kr -= nA2;
    __syncthreads();

    // round 3: bits [7:0], restricted to top24 == (T1<<12)|T2
    const unsigned pre24 = ((unsigned)T1 << 12) | (unsigned)T2;
    for (int i = tid; i < 256; i += NTH) hist[i] = 0u;
    __syncthreads();
    for (int i = tid; i < F_; i += NTH) {
        const unsigned k = sk[i];
        if ((k >> 8) == pre24) atomicAdd(&hist[k & 0xFFu], 1u);
    }
    __syncthreads();
    suffix_scan(hist, 256);
    const int T3 = find_T(hist, 256, Kr, &sh->T);
    const unsigned nA3 = (T3 < 255) ? hist[T3 + 1] : 0u;
    const int needEq = (int)(Kr - nA3);
    const unsigned kth = (pre24 << 8) | (unsigned)T3;
    __syncthreads();

    // collect: all keys > kth, plus needEq keys == kth (lowest index first)
    if (tid == 0) { sh->nsel = 0; sh->neq = 0; }
    __syncthreads();
    for (int i = tid; i < F_; i += NTH) {
        const unsigned k = sk[i];
        if (k > kth) {
            const int p = atomicAdd(&sh->nsel, 1);
            selIdx[p] = i;
        } else if (k == kth) {
            const int p = atomicAdd(&sh->neq, 1);
            if (p < 64) eqIdx[p] = i;
        }
    }
    __syncthreads();
    if (tid == 0) {
        int m = sh->neq; if (m > 64) m = 64;
        for (int a = 1; a < m; a++) {           // tiny insertion sort by index
            int v = eqIdx[a]; int c = a - 1;
            while (c >= 0 && eqIdx[c] > v) { eqIdx[c + 1] = eqIdx[c]; c--; }
            eqIdx[c + 1] = v;
        }
        const int base = sh->nsel;
        for (int a = 0; a < needEq; a++)
            selIdx[base + a] = (a < m) ? eqIdx[a] : eqIdx[0];
    }
    __syncthreads();
}

__global__ __launch_bounds__(NTH)
void row_kernel(const float* __restrict__ noise,
                const int*   __restrict__ last_usage,
                const float* __restrict__ lookup,
                const float* __restrict__ bias,
                float* __restrict__ out)
{
    extern __shared__ unsigned char smem_raw[];
    float*    sp     = (float*)smem_raw;                                  // F_
    unsigned* sk     = (unsigned*)(smem_raw + (size_t)F_ * 4);            // F_
    unsigned* hist   = (unsigned*)(smem_raw + (size_t)F_ * 8);            // 4096
    int*      selIdx = (int*)(smem_raw + (size_t)F_ * 8 + 4096 * 4);      // 256
    int*      eqIdx  = (int*)((char*)selIdx + 256 * 4);                   // 64

    __shared__ SelShared sh;
    __shared__ int   feats32[K1];
    __shared__ float w32[K1];
    __shared__ float uw[K2_];

    const int tid = threadIdx.x;
    const int b   = blockIdx.x;

    // load this row of project into smem
    const float* prow = g_project + (size_t)b * F_;
    for (int i = tid; i < F_; i += NTH) sp[i] = prow[i];

    // fuzz = std(project, ddof=1) * FUZZ_FACTOR(=1)
    const double S  = g_sum;
    const double SS = g_sumsq;
    const double N  = (double)B_ * (double)F_;
    const float fuzz = (float)sqrt((SS - S * S / N) / (N - 1.0));

    // ---- pass 1: top-32 of project ----
    __syncthreads();
    for (int i = tid; i < F_; i += NTH) sk[i] = fkey(sp[i]);
    __syncthreads();
    select_topk(sk, hist, selIdx, eqIdx, K1, &sh);
    for (int j = tid; j < K1; j += NTH) {
        feats32[j] = selIdx[j];
        w32[j]     = sp[selIdx[j]];
    }
    __syncthreads();

    // ---- pass 2: top-256 of fuzzed dead features ----
    const float* nrow = noise + (size_t)b * F_;
    for (int i = tid; i < F_; i += NTH)
        sk[i] = (last_usage[i] > DEAD_CUT) ? fkey(sp[i] + fuzz * nrow[i]) : 0u;
    __syncthreads();
    select_topk(sk, hist, selIdx, eqIdx, K2_, &sh);
    for (int j = tid; j < K2_; j += NTH) uw[j] = sp[selIdx[j]];   // weight = project value
    __syncthreads();

    // ---- reconstruction ----
    for (int d = tid; d < D_; d += NTH) {
        float a = bias[d];
#pragma unroll 8
        for (int k = 0; k < K1; k++)
            a += w32[k] * lookup[(size_t)feats32[k] * D_ + d];
        out[(size_t)b * D_ + d] = a;

        float a0 = 0.f, a1 = 0.f, a2 = 0.f, a3 = 0.f;
#pragma unroll 2
        for (int k = 0; k < K2_; k += 4) {
            a0 += uw[k + 0] * lookup[(size_t)selIdx[k + 0] * D_ + d];
            a1 += uw[k + 1] * lookup[(size_t)selIdx[k + 1] * D_ + d];
            a2 += uw[k + 2] * lookup[(size_t)selIdx[k + 2] * D_ + d];
            a3 += uw[k + 3] * lookup[(size_t)selIdx[k + 3] * D_ + d];
        }
        out[(size_t)B_ * D_ + (size_t)b * D_ + d] = (a0 + a1) + (a2 + a3);
    }
}

// ---------------------------------------------------------------------------
// Launch
// ---------------------------------------------------------------------------
extern "C" void kernel_launch(void* const* d_in, const int* in_sizes, int n_in,
                              void* d_out, int out_size)
{
    (void)in_sizes; (void)n_in; (void)out_size;
    const float* embed      = (const float*)d_in[0];
    const float* enc_bias   = (const float*)d_in[1];
    const float* enc_W      = (const float*)d_in[2];
    const float* lookup     = (const float*)d_in[3];
    const float* noise      = (const float*)d_in[4];
    const int*   last_usage = (const int*)  d_in[5];
    float* out = (float*)d_out;

    const size_t smem_bytes = (size_t)F_ * 8 + 4096 * 4 + 256 * 4 + 64 * 4; // 214272
    cudaFuncSetAttribute(row_kernel,
                         cudaFuncAttributeMaxDynamicSharedMemorySize,
                         (int)smem_bytes);

    zero_stats_kernel<<<1, 1>>>();
    gemm_kernel<<<dim3(F_ / BN, B_ / BM), 256>>>(embed, enc_bias, enc_W);
    row_kernel<<<B_, NTH, smem_bytes>>>(noise, last_usage, lookup, enc_bias, out);
}

// round 12
// speedup vs baseline: 1.9471x; 1.9471x over previous
#include <cuda_runtime.h>
#include <math.h>

#define B_   4096
#define D_   1024
#define F_   24576
#define K1   32      /* TOPK */
#define K2_  256     /* DEAD_TOPK */
#define DEAD_CUT 100000
#define NTH  512     /* threads in row kernel */

#define GRID_X (F_ / 128)
#define GRID_Y (B_ / 128)
#define NBLK   (GRID_X * GRID_Y)

// ---------------------------------------------------------------------------
// Scratch (device globals: no cudaMalloc allowed)
// ---------------------------------------------------------------------------
__device__ float  g_project[(size_t)B_ * (size_t)F_];   // 402 MB
__device__ double g_part[NBLK][2];                      // per-CTA (sum, sumsq)
__device__ double g_sum;
__device__ double g_sumsq;

// Deterministic reduction of per-CTA partials -> g_sum / g_sumsq.
// Pure overwrite (no zero-init, no atomics): graph-replay safe.
__global__ __launch_bounds__(512)
void reduce_stats_kernel() {
    const int tid = threadIdx.x;
    double s = 0.0, ss = 0.0;
    for (int i = tid; i < NBLK; i += 512) {
        s  += g_part[i][0];
        ss += g_part[i][1];
    }
    __shared__ double sh_s[512], sh_ss[512];
    sh_s[tid] = s; sh_ss[tid] = ss;
    __syncthreads();
    for (int off = 256; off > 0; off >>= 1) {
        if (tid < off) {
            sh_s[tid]  += sh_s[tid + off];
            sh_ss[tid] += sh_ss[tid + off];
        }
        __syncthreads();
    }
    if (tid == 0) { g_sum = sh_s[0]; g_sumsq = sh_ss[0]; }
}

// ---------------------------------------------------------------------------
// packed f32x2 helpers (SASS FFMA2 — only reachable via PTX fma.rn.f32x2)
// Each half is an IEEE fp32 FMA: bit-identical math to scalar FFMA.
// ---------------------------------------------------------------------------
__device__ __forceinline__ void fma2(unsigned long long& d,
                                     unsigned long long a,
                                     unsigned long long b) {
    asm("fma.rn.f32x2 %0, %1, %2, %0;" : "+l"(d) : "l"(a), "l"(b));
}
__device__ __forceinline__ void add2(unsigned long long& d,
                                     unsigned long long a) {
    asm("add.rn.f32x2 %0, %0, %1;" : "+l"(d) : "l"(a));
}
__device__ __forceinline__ unsigned long long dupf(float x) {
    unsigned long long r;
    asm("mov.b64 %0, {%1, %1};" : "=l"(r) : "f"(x));
    return r;
}
__device__ __forceinline__ void unpack2(unsigned long long v, float& lo, float& hi) {
    asm("mov.b64 {%0, %1}, %2;" : "=f"(lo), "=f"(hi) : "l"(v));
}

// ---------------------------------------------------------------------------
// SGEMM: project[b,f] = sum_d (embed[b,d]-bias[d]) * W[f,d]
// 128x128 tile, BK=16, 256 threads, 8x8 micro-tile, double buffered.
// Memory path IDENTICAL to the scalar R8 kernel (conflict-free, 64B/thr/kk).
// Mainloop packs rows (2p,2p+1) into fma.rn.f32x2 accumulators; A pairs come
// directly from the 128-bit smem loads, B is duplicated in REGISTERS only.
// Per-element fp32 op sequence identical to scalar version -> bit-exact.
// Per-CTA stats partials written without atomics.
// ---------------------------------------------------------------------------
#define BM 128
#define BN 128
#define BK 16

__global__ __launch_bounds__(256, 1)
void gemm_kernel(const float* __restrict__ embed,
                 const float* __restrict__ bias,
                 const float* __restrict__ W)
{
    __shared__ __align__(16) float As[2][BK][BM];
    __shared__ __align__(16) float Bs[2][BK][BN];

    const int tid  = threadIdx.x;
    const int row0 = blockIdx.y * BM;   // batch rows
    const int col0 = blockIdx.x * BN;   // feature cols

    // loader mapping: each thread loads 2 float4 for A and 2 for B per stage
    const int ar0 = tid >> 2;                 // rows 0..63
    const int ar1 = (tid + 256) >> 2;         // rows 64..127
    const int aq  = tid & 3;                  // which float4 of the 16-wide k slab

    const float* Ap0 = embed + (size_t)(row0 + ar0) * D_ + aq * 4;
    const float* Ap1 = embed + (size_t)(row0 + ar1) * D_ + aq * 4;
    const float* Bp0 = W     + (size_t)(col0 + ar0) * D_ + aq * 4;
    const float* Bp1 = W     + (size_t)(col0 + ar1) * D_ + aq * 4;

    // paired accumulators: acc2[p][j] holds rows (2p, 2p+1) of column j
    unsigned long long acc2[4][8];
#pragma unroll
    for (int p = 0; p < 4; p++)
#pragma unroll
        for (int j = 0; j < 8; j++) acc2[p][j] = 0ull;

    float4 a0, a1, b0, b1, bb;

    // preload tile 0
    a0 = *(const float4*)(Ap0);
    a1 = *(const float4*)(Ap1);
    b0 = *(const float4*)(Bp0);
    b1 = *(const float4*)(Bp1);
    bb = *(const float4*)(bias + aq * 4);

    int buf = 0;
    {
        const int kc = aq * 4;
        As[0][kc+0][ar0] = a0.x - bb.x;  As[0][kc+1][ar0] = a0.y - bb.y;
        As[0][kc+2][ar0] = a0.z - bb.z;  As[0][kc+3][ar0] = a0.w - bb.w;
        As[0][kc+0][ar1] = a1.x - bb.x;  As[0][kc+1][ar1] = a1.y - bb.y;
        As[0][kc+2][ar1] = a1.z - bb.z;  As[0][kc+3][ar1] = a1.w - bb.w;
        Bs[0][kc+0][ar0] = b0.x;  Bs[0][kc+1][ar0] = b0.y;
        Bs[0][kc+2][ar0] = b0.z;  Bs[0][kc+3][ar0] = b0.w;
        Bs[0][kc+0][ar1] = b1.x;  Bs[0][kc+1][ar1] = b1.y;
        Bs[0][kc+2][ar1] = b1.z;  Bs[0][kc+3][ar1] = b1.w;
    }
    __syncthreads();

    const int ty = tid >> 4;   // 0..15
    const int tx = tid & 15;   // 0..15
    const int NT = D_ / BK;    // 64

    for (int t = 0; t < NT; t++) {
        if (t + 1 < NT) {
            const int k0 = (t + 1) * BK;
            a0 = *(const float4*)(Ap0 + k0);
            a1 = *(const float4*)(Ap1 + k0);
            b0 = *(const float4*)(Bp0 + k0);
            b1 = *(const float4*)(Bp1 + k0);
            bb = *(const float4*)(bias + k0 + aq * 4);
        }
        // per-tile partial sums (fresh registers -> short rounding chains)
        unsigned long long ts2[4][8];
#pragma unroll
        for (int p = 0; p < 4; p++)
#pragma unroll
            for (int j = 0; j < 8; j++) ts2[p][j] = 0ull;

#pragma unroll
        for (int kk = 0; kk < BK; kk++) {
            // A pairs (af[2p], af[2p+1]) straight from the 128-bit loads
            ulonglong2 pa0 = *(const ulonglong2*)&As[buf][kk][ty * 8];
            ulonglong2 pa1 = *(const ulonglong2*)&As[buf][kk][ty * 8 + 4];
            unsigned long long a2[4] = { pa0.x, pa0.y, pa1.x, pa1.y };
            // B: original conflict-free layout, duplicate in registers
            float4 f0 = *(const float4*)&Bs[buf][kk][tx * 8];
            float4 f1 = *(const float4*)&Bs[buf][kk][tx * 8 + 4];
            unsigned long long b2[8] = {
                dupf(f0.x), dupf(f0.y), dupf(f0.z), dupf(f0.w),
                dupf(f1.x), dupf(f1.y), dupf(f1.z), dupf(f1.w)
            };
#pragma unroll
            for (int p = 0; p < 4; p++)
#pragma unroll
                for (int j = 0; j < 8; j++)
                    fma2(ts2[p][j], a2[p], b2[j]);
        }
#pragma unroll
        for (int p = 0; p < 4; p++)
#pragma unroll
            for (int j = 0; j < 8; j++)
                add2(acc2[p][j], ts2[p][j]);

        if (t + 1 < NT) {
            const int nb = buf ^ 1;
            const int kc = aq * 4;
            As[nb][kc+0][ar0] = a0.x - bb.x;  As[nb][kc+1][ar0] = a0.y - bb.y;
            As[nb][kc+2][ar0] = a0.z - bb.z;  As[nb][kc+3][ar0] = a0.w - bb.w;
            As[nb][kc+0][ar1] = a1.x - bb.x;  As[nb][kc+1][ar1] = a1.y - bb.y;
            As[nb][kc+2][ar1] = a1.z - bb.z;  As[nb][kc+3][ar1] = a1.w - bb.w;
            Bs[nb][kc+0][ar0] = b0.x;  Bs[nb][kc+1][ar0] = b0.y;
            Bs[nb][kc+2][ar0] = b0.z;  Bs[nb][kc+3][ar0] = b0.w;
            Bs[nb][kc+0][ar1] = b1.x;  Bs[nb][kc+1][ar1] = b1.y;
            Bs[nb][kc+2][ar1] = b1.z;  Bs[nb][kc+3][ar1] = b1.w;
            __syncthreads();
            buf = nb;
        }
    }

    // unpack pairs back to scalar accumulators (lo = row 2p, hi = row 2p+1)
    float acc[8][8];
#pragma unroll
    for (int p = 0; p < 4; p++)
#pragma unroll
        for (int j = 0; j < 8; j++)
            unpack2(acc2[p][j], acc[2*p][j], acc[2*p+1][j]);

    // write C + accumulate stats (identical order to scalar version)
    float s = 0.0f, ss = 0.0f;
#pragma unroll
    for (int i = 0; i < 8; i++) {
        const size_t base = (size_t)(row0 + ty * 8 + i) * F_ + (col0 + tx * 8);
        float4 c0 = make_float4(acc[i][0], acc[i][1], acc[i][2], acc[i][3]);
        float4 c1 = make_float4(acc[i][4], acc[i][5], acc[i][6], acc[i][7]);
        *(float4*)&g_project[base]     = c0;
        *(float4*)&g_project[base + 4] = c1;
#pragma unroll
        for (int j = 0; j < 8; j++) { float v = acc[i][j]; s += v; ss += v * v; }
    }
#pragma unroll
    for (int o = 16; o > 0; o >>= 1) {
        s  += __shfl_down_sync(0xffffffffu, s,  o);
        ss += __shfl_down_sync(0xffffffffu, ss, o);
    }
    __shared__ double wsum[8], wss[8];
    const int w = tid >> 5, l = tid & 31;
    if (l == 0) { wsum[w] = (double)s; wss[w] = (double)ss; }
    __syncthreads();
    if (tid == 0) {
        double S = 0.0, SS = 0.0;
        for (int i = 0; i < 8; i++) { S += wsum[i]; SS += wss[i]; }
        const int bid = blockIdx.y * gridDim.x + blockIdx.x;
        g_part[bid][0] = S;
        g_part[bid][1] = SS;
    }
}

// ---------------------------------------------------------------------------
// Per-row top-k (exact radix select on monotone float keys) + reconstruction
// ---------------------------------------------------------------------------
__device__ __forceinline__ unsigned fkey(float v) {
    unsigned u = __float_as_uint(v);
    return (u & 0x80000000u) ? ~u : (u | 0x80000000u);
}

struct SelShared { int T; int nsel; int neq; };

__device__ void suffix_scan(unsigned* h, int NB) {
    const int tid = threadIdx.x;
    for (int off = 1; off < NB; off <<= 1) {
        unsigned v[8];
        int c = 0;
        for (int idx = tid; idx < NB; idx += NTH) {
            const int srcIdx = idx + off;
            v[c++] = (srcIdx < NB) ? h[srcIdx] : 0u;
        }
        __syncthreads();
        c = 0;
        for (int idx = tid; idx < NB; idx += NTH) h[idx] += v[c++];
        __syncthreads();
    }
}

__device__ int find_T(unsigned* h, int NB, unsigned K, int* sT) {
    const int tid = threadIdx.x;
    for (int idx = tid; idx < NB; idx += NTH)
        if (h[idx] >= K && (idx == NB - 1 || h[idx + 1] < K)) *sT = idx;
    __syncthreads();
    return *sT;
}

// exact top-K of keys sk[0..F_) -> indices in selIdx[0..K)
__device__ void select_topk(const unsigned* sk, unsigned* hist,
                            int* selIdx, int* eqIdx, int K, SelShared* sh)
{
    const int tid = threadIdx.x;
    const unsigned Ku = (unsigned)K;

    // round 1: key bits [31:20]
    for (int i = tid; i < 4096; i += NTH) hist[i] = 0u;
    __syncthreads();
    for (int i = tid; i < F_; i += NTH) atomicAdd(&hist[sk[i] >> 20], 1u);
    __syncthreads();
    suffix_scan(hist, 4096);
    const int T1 = find_T(hist, 4096, Ku, &sh->T);
    const unsigned nA1 = (T1 < 4095) ? hist[T1 + 1] : 0u;
    unsigned Kr = Ku - nA1;
    __syncthreads();

    // round 2: bits [19:8], restricted to top12 == T1
    for (int i = tid; i < 4096; i += NTH) hist[i] = 0u;
    __syncthreads();
    for (int i = tid; i < F_; i += NTH) {
        const unsigned k = sk[i];
        if ((int)(k >> 20) == T1) atomicAdd(&hist[(k >> 8) & 0xFFFu], 1u);
    }
    __syncthreads();
    suffix_scan(hist, 4096);
    const int T2 = find_T(hist, 4096, Kr, &sh->T);
    const unsigned nA2 = (T2 < 4095) ? hist[T2 + 1] : 0u;
    Kr -= nA2;
    __syncthreads();

    // round 3: bits [7:0], restricted to top24 == (T1<<12)|T2
    const unsigned pre24 = ((unsigned)T1 << 12) | (unsigned)T2;
    for (int i = tid; i < 256; i += NTH) hist[i] = 0u;
    __syncthreads();
    for (int i = tid; i < F_; i += NTH) {
        const unsigned k = sk[i];
        if ((k >> 8) == pre24) atomicAdd(&hist[k & 0xFFu], 1u);
    }
    __syncthreads();
    suffix_scan(hist, 256);
    const int T3 = find_T(hist, 256, Kr, &sh->T);
    const unsigned nA3 = (T3 < 255) ? hist[T3 + 1] : 0u;
    const int needEq = (int)(Kr - nA3);
    const unsigned kth = (pre24 << 8) | (unsigned)T3;
    __syncthreads();

    // collect: all keys > kth, plus needEq keys == kth (lowest index first)
    if (tid == 0) { sh->nsel = 0; sh->neq = 0; }
    __syncthreads();
    for (int i = tid; i < F_; i += NTH) {
        const unsigned k = sk[i];
        if (k > kth) {
            const int p = atomicAdd(&sh->nsel, 1);
            selIdx[p] = i;
        } else if (k == kth) {
            const int p = atomicAdd(&sh->neq, 1);
            if (p < 64) eqIdx[p] = i;
        }
    }
    __syncthreads();
    if (tid == 0) {
        int m = sh->neq; if (m > 64) m = 64;
        for (int a = 1; a < m; a++) {           // tiny insertion sort by index
            int v = eqIdx[a]; int c = a - 1;
            while (c >= 0 && eqIdx[c] > v) { eqIdx[c + 1] = eqIdx[c]; c--; }
            eqIdx[c + 1] = v;
        }
        const int base = sh->nsel;
        for (int a = 0; a < needEq; a++)
            selIdx[base + a] = (a < m) ? eqIdx[a] : eqIdx[0];
    }
    __syncthreads();
}

__global__ __launch_bounds__(NTH)
void row_kernel(const float* __restrict__ noise,
                const int*   __restrict__ last_usage,
                const float* __restrict__ lookup,
                const float* __restrict__ bias,
                float* __restrict__ out)
{
    extern __shared__ unsigned char smem_raw[];
    float*    sp     = (float*)smem_raw;                                  // F_
    unsigned* sk     = (unsigned*)(smem_raw + (size_t)F_ * 4);            // F_
    unsigned* hist   = (unsigned*)(smem_raw + (size_t)F_ * 8);            // 4096
    int*      selIdx = (int*)(smem_raw + (size_t)F_ * 8 + 4096 * 4);      // 256
    int*      eqIdx  = (int*)((char*)selIdx + 256 * 4);                   // 64

    __shared__ SelShared sh;
    __shared__ int   feats32[K1];
    __shared__ float w32[K1];
    __shared__ float uw[K2_];

    const int tid = threadIdx.x;
    const int b   = blockIdx.x;

    // load this row of project into smem
    const float* prow = g_project + (size_t)b * F_;
    for (int i = tid; i < F_; i += NTH) sp[i] = prow[i];

    // fuzz = std(project, ddof=1) * FUZZ_FACTOR(=1)
    const double S  = g_sum;
    const double SS = g_sumsq;
    const double N  = (double)B_ * (double)F_;
    const float fuzz = (float)sqrt((SS - S * S / N) / (N - 1.0));

    // ---- pass 1: top-32 of project ----
    __syncthreads();
    for (int i = tid; i < F_; i += NTH) sk[i] = fkey(sp[i]);
    __syncthreads();
    select_topk(sk, hist, selIdx, eqIdx, K1, &sh);
    for (int j = tid; j < K1; j += NTH) {
        feats32[j] = selIdx[j];
        w32[j]     = sp[selIdx[j]];
    }
    __syncthreads();

    // ---- pass 2: top-256 of fuzzed dead features ----
    const float* nrow = noise + (size_t)b * F_;
    for (int i = tid; i < F_; i += NTH)
        sk[i] = (last_usage[i] > DEAD_CUT) ? fkey(sp[i] + fuzz * nrow[i]) : 0u;
    __syncthreads();
    select_topk(sk, hist, selIdx, eqIdx, K2_, &sh);
    for (int j = tid; j < K2_; j += NTH) uw[j] = sp[selIdx[j]];   // weight = project value
    __syncthreads();

    // ---- reconstruction ----
    for (int d = tid; d < D_; d += NTH) {
        float a = bias[d];
#pragma unroll 8
        for (int k = 0; k < K1; k++)
            a += w32[k] * lookup[(size_t)feats32[k] * D_ + d];
        out[(size_t)b * D_ + d] = a;

        float a0 = 0.f, a1 = 0.f, a2 = 0.f, a3 = 0.f;
#pragma unroll 2
        for (int k = 0; k < K2_; k += 4) {
            a0 += uw[k + 0] * lookup[(size_t)selIdx[k + 0] * D_ + d];
            a1 += uw[k + 1] * lookup[(size_t)selIdx[k + 1] * D_ + d];
            a2 += uw[k + 2] * lookup[(size_t)selIdx[k + 2] * D_ + d];
            a3 += uw[k + 3] * lookup[(size_t)selIdx[k + 3] * D_ + d];
        }
        out[(size_t)B_ * D_ + (size_t)b * D_ + d] = (a0 + a1) + (a2 + a3);
    }
}

// ---------------------------------------------------------------------------
// Launch
// ---------------------------------------------------------------------------
extern "C" void kernel_launch(void* const* d_in, const int* in_sizes, int n_in,
                              void* d_out, int out_size)
{
    (void)in_sizes; (void)n_in; (void)out_size;
    const float* embed      = (const float*)d_in[0];
    const float* enc_bias   = (const float*)d_in[1];
    const float* enc_W      = (const float*)d_in[2];
    const float* lookup     = (const float*)d_in[3];
    const float* noise      = (const float*)d_in[4];
    const int*   last_usage = (const int*)  d_in[5];
    float* out = (float*)d_out;

    const size_t smem_bytes = (size_t)F_ * 8 + 4096 * 4 + 256 * 4 + 64 * 4; // 214272
    cudaFuncSetAttribute(row_kernel,
                         cudaFuncAttributeMaxDynamicSharedMemorySize,
                         (int)smem_bytes);

    gemm_kernel<<<dim3(GRID_X, GRID_Y), 256>>>(embed, enc_bias, enc_W);
    reduce_stats_kernel<<<1, 512>>>();
    row_kernel<<<B_, NTH, smem_bytes>>>(noise, last_usage, lookup, enc_bias, out);
}

// round 13
// speedup vs baseline: 2.0682x; 1.0622x over previous
#include <cuda_runtime.h>
#include <math.h>

#define B_   4096
#define D_   1024
#define F_   24576
#define K1   32      /* TOPK */
#define K2_  256     /* DEAD_TOPK */
#define DEAD_CUT 100000
#define NTH  512     /* threads in row kernel */

#define GRID_X (F_ / 128)
#define GRID_Y (B_ / 128)
#define NBLK   (GRID_X * GRID_Y)

// ---------------------------------------------------------------------------
// Scratch (device globals: no cudaMalloc allowed)
// ---------------------------------------------------------------------------
__device__ float  g_project[(size_t)B_ * (size_t)F_];   // 402 MB
__device__ double g_part[NBLK][2];                      // per-CTA (sum, sumsq)
__device__ double g_sum;
__device__ double g_sumsq;

// Deterministic reduction of per-CTA partials -> g_sum / g_sumsq.
__global__ __launch_bounds__(512)
void reduce_stats_kernel() {
    const int tid = threadIdx.x;
    double s = 0.0, ss = 0.0;
    for (int i = tid; i < NBLK; i += 512) {
        s  += g_part[i][0];
        ss += g_part[i][1];
    }
    __shared__ double sh_s[512], sh_ss[512];
    sh_s[tid] = s; sh_ss[tid] = ss;
    __syncthreads();
    for (int off = 256; off > 0; off >>= 1) {
        if (tid < off) {
            sh_s[tid]  += sh_s[tid + off];
            sh_ss[tid] += sh_ss[tid + off];
        }
        __syncthreads();
    }
    if (tid == 0) { g_sum = sh_s[0]; g_sumsq = sh_ss[0]; }
}

// ---------------------------------------------------------------------------
// packed f32x2 helpers (SASS FFMA2). Each half is an IEEE fp32 FMA.
// ---------------------------------------------------------------------------
__device__ __forceinline__ void fma2(unsigned long long& d,
                                     unsigned long long a,
                                     unsigned long long b) {
    asm("fma.rn.f32x2 %0, %1, %2, %0;" : "+l"(d) : "l"(a), "l"(b));
}
__device__ __forceinline__ void add2(unsigned long long& d,
                                     unsigned long long a) {
    asm("add.rn.f32x2 %0, %0, %1;" : "+l"(d) : "l"(a));
}
__device__ __forceinline__ unsigned long long dupf(float x) {
    unsigned long long r;
    asm("mov.b64 %0, {%1, %1};" : "=l"(r) : "f"(x));
    return r;
}
__device__ __forceinline__ void unpack2(unsigned long long v, float& lo, float& hi) {
    asm("mov.b64 {%0, %1}, %2;" : "=f"(lo), "=f"(hi) : "l"(v));
}

// XOR swizzle of 16-byte chunks within a 128-float Bs row: chunk q -> q ^ ((q>>3)&1).
// Makes the 32-B-stride fragment loads (LDS.128 at tx*32 bytes) bank-conflict-free
// in every 8-lane quarter, for both the even (f0) and odd (f1) chunk streams.
__device__ __forceinline__ int bswiz(int c) {
    int q = c >> 2;
    q ^= (q >> 3) & 1;
    return (q << 2) | (c & 3);
}

// ---------------------------------------------------------------------------
// SGEMM: project[b,f] = sum_d (embed[b,d]-bias[d]) * W[f,d]
// 128x128 tile, BK=16, 256 threads, 8x8 micro-tile, smem double buffered.
// FFMA2 mainloop (rows paired in accumulators), B duplicated in registers.
// This round: Bs column swizzle (conflict-free B loads) + 2-deep register
// pipeline over kk. FP op sequence per element identical to R8/R12 -> bit-exact.
// ---------------------------------------------------------------------------
#define BM 128
#define BN 128
#define BK 16

__global__ __launch_bounds__(256, 1)
void gemm_kernel(const float* __restrict__ embed,
                 const float* __restrict__ bias,
                 const float* __restrict__ W)
{
    __shared__ __align__(16) float As[2][BK][BM];
    __shared__ __align__(16) float Bs[2][BK][BN];

    const int tid  = threadIdx.x;
    const int row0 = blockIdx.y * BM;   // batch rows
    const int col0 = blockIdx.x * BN;   // feature cols

    // loader mapping: each thread loads 2 float4 for A and 2 for B per stage
    const int ar0 = tid >> 2;                 // rows 0..63
    const int ar1 = (tid + 256) >> 2;         // rows 64..127
    const int aq  = tid & 3;                  // which float4 of the 16-wide k slab

    // swizzled store columns for B
    const int br0s = bswiz(ar0);
    const int br1s = bswiz(ar1);

    const float* Ap0 = embed + (size_t)(row0 + ar0) * D_ + aq * 4;
    const float* Ap1 = embed + (size_t)(row0 + ar1) * D_ + aq * 4;
    const float* Bp0 = W     + (size_t)(col0 + ar0) * D_ + aq * 4;
    const float* Bp1 = W     + (size_t)(col0 + ar1) * D_ + aq * 4;

    // paired accumulators: acc2[p][j] holds rows (2p, 2p+1) of column j
    unsigned long long acc2[4][8];
#pragma unroll
    for (int p = 0; p < 4; p++)
#pragma unroll
        for (int j = 0; j < 8; j++) acc2[p][j] = 0ull;

    float4 a0, a1, b0, b1, bb;

    // preload tile 0
    a0 = *(const float4*)(Ap0);
    a1 = *(const float4*)(Ap1);
    b0 = *(const float4*)(Bp0);
    b1 = *(const float4*)(Bp1);
    bb = *(const float4*)(bias + aq * 4);

    int buf = 0;
    {
        const int kc = aq * 4;
        As[0][kc+0][ar0] = a0.x - bb.x;  As[0][kc+1][ar0] = a0.y - bb.y;
        As[0][kc+2][ar0] = a0.z - bb.z;  As[0][kc+3][ar0] = a0.w - bb.w;
        As[0][kc+0][ar1] = a1.x - bb.x;  As[0][kc+1][ar1] = a1.y - bb.y;
        As[0][kc+2][ar1] = a1.z - bb.z;  As[0][kc+3][ar1] = a1.w - bb.w;
        Bs[0][kc+0][br0s] = b0.x;  Bs[0][kc+1][br0s] = b0.y;
        Bs[0][kc+2][br0s] = b0.z;  Bs[0][kc+3][br0s] = b0.w;
        Bs[0][kc+0][br1s] = b1.x;  Bs[0][kc+1][br1s] = b1.y;
        Bs[0][kc+2][br1s] = b1.z;  Bs[0][kc+3][br1s] = b1.w;
    }
    __syncthreads();

    const int ty = tid >> 4;   // 0..15
    const int tx = tid & 15;   // 0..15
    const int NT = D_ / BK;    // 64

    // swizzled load columns for the two B fragments (16-B aligned chunks)
    const int txs0 = bswiz(tx * 8);
    const int txs1 = bswiz(tx * 8 + 4);

    for (int t = 0; t < NT; t++) {
        if (t + 1 < NT) {
            const int k0 = (t + 1) * BK;
            a0 = *(const float4*)(Ap0 + k0);
            a1 = *(const float4*)(Ap1 + k0);
            b0 = *(const float4*)(Bp0 + k0);
            b1 = *(const float4*)(Bp1 + k0);
            bb = *(const float4*)(bias + k0 + aq * 4);
        }
        // per-tile partial sums (fresh registers -> short rounding chains)
        unsigned long long ts2[4][8];
#pragma unroll
        for (int p = 0; p < 4; p++)
#pragma unroll
            for (int j = 0; j < 8; j++) ts2[p][j] = 0ull;

        // 2-deep register pipeline over kk: fragments for kk+1 are loaded
        // before the FFMA2 block of kk consumes stage kk&1.
        unsigned long long fa[2][4];
        float4 ff0[2], ff1[2];
        {
            ulonglong2 pa0 = *(const ulonglong2*)&As[buf][0][ty * 8];
            ulonglong2 pa1 = *(const ulonglong2*)&As[buf][0][ty * 8 + 4];
            fa[0][0] = pa0.x; fa[0][1] = pa0.y; fa[0][2] = pa1.x; fa[0][3] = pa1.y;
            ff0[0] = *(const float4*)&Bs[buf][0][txs0];
            ff1[0] = *(const float4*)&Bs[buf][0][txs1];
        }
#pragma unroll
        for (int kk = 0; kk < BK; kk++) {
            const int cur = kk & 1;
            if (kk + 1 < BK) {
                const int nxt = cur ^ 1;
                ulonglong2 pa0 = *(const ulonglong2*)&As[buf][kk+1][ty * 8];
                ulonglong2 pa1 = *(const ulonglong2*)&As[buf][kk+1][ty * 8 + 4];
                fa[nxt][0] = pa0.x; fa[nxt][1] = pa0.y;
                fa[nxt][2] = pa1.x; fa[nxt][3] = pa1.y;
                ff0[nxt] = *(const float4*)&Bs[buf][kk+1][txs0];
                ff1[nxt] = *(const float4*)&Bs[buf][kk+1][txs1];
            }
            unsigned long long b2[8] = {
                dupf(ff0[cur].x), dupf(ff0[cur].y), dupf(ff0[cur].z), dupf(ff0[cur].w),
                dupf(ff1[cur].x), dupf(ff1[cur].y), dupf(ff1[cur].z), dupf(ff1[cur].w)
            };
#pragma unroll
            for (int p = 0; p < 4; p++)
#pragma unroll
                for (int j = 0; j < 8; j++)
                    fma2(ts2[p][j], fa[cur][p], b2[j]);
        }
#pragma unroll
        for (int p = 0; p < 4; p++)
#pragma unroll
            for (int j = 0; j < 8; j++)
                add2(acc2[p][j], ts2[p][j]);

        if (t + 1 < NT) {
            const int nb = buf ^ 1;
            const int kc = aq * 4;
            As[nb][kc+0][ar0] = a0.x - bb.x;  As[nb][kc+1][ar0] = a0.y - bb.y;
            As[nb][kc+2][ar0] = a0.z - bb.z;  As[nb][kc+3][ar0] = a0.w - bb.w;
            As[nb][kc+0][ar1] = a1.x - bb.x;  As[nb][kc+1][ar1] = a1.y - bb.y;
            As[nb][kc+2][ar1] = a1.z - bb.z;  As[nb][kc+3][ar1] = a1.w - bb.w;
            Bs[nb][kc+0][br0s] = b0.x;  Bs[nb][kc+1][br0s] = b0.y;
            Bs[nb][kc+2][br0s] = b0.z;  Bs[nb][kc+3][br0s] = b0.w;
            Bs[nb][kc+0][br1s] = b1.x;  Bs[nb][kc+1][br1s] = b1.y;
            Bs[nb][kc+2][br1s] = b1.z;  Bs[nb][kc+3][br1s] = b1.w;
            __syncthreads();
            buf = nb;
        }
    }

    // unpack pairs back to scalar accumulators (lo = row 2p, hi = row 2p+1)
    float acc[8][8];
#pragma unroll
    for (int p = 0; p < 4; p++)
#pragma unroll
        for (int j = 0; j < 8; j++)
            unpack2(acc2[p][j], acc[2*p][j], acc[2*p+1][j]);

    // write C + accumulate stats (identical order to scalar version)
    float s = 0.0f, ss = 0.0f;
#pragma unroll
    for (int i = 0; i < 8; i++) {
        const size_t base = (size_t)(row0 + ty * 8 + i) * F_ + (col0 + tx * 8);
        float4 c0 = make_float4(acc[i][0], acc[i][1], acc[i][2], acc[i][3]);
        float4 c1 = make_float4(acc[i][4], acc[i][5], acc[i][6], acc[i][7]);
        *(float4*)&g_project[base]     = c0;
        *(float4*)&g_project[base + 4] = c1;
#pragma unroll
        for (int j = 0; j < 8; j++) { float v = acc[i][j]; s += v; ss += v * v; }
    }
#pragma unroll
    for (int o = 16; o > 0; o >>= 1) {
        s  += __shfl_down_sync(0xffffffffu, s,  o);
        ss += __shfl_down_sync(0xffffffffu, ss, o);
    }
    __shared__ double wsum[8], wss[8];
    const int w = tid >> 5, l = tid & 31;
    if (l == 0) { wsum[w] = (double)s; wss[w] = (double)ss; }
    __syncthreads();
    if (tid == 0) {
        double S = 0.0, SS = 0.0;
        for (int i = 0; i < 8; i++) { S += wsum[i]; SS += wss[i]; }
        const int bid = blockIdx.y * gridDim.x + blockIdx.x;
        g_part[bid][0] = S;
        g_part[bid][1] = SS;
    }
}

// ---------------------------------------------------------------------------
// Per-row top-k (exact radix select on monotone float keys) + reconstruction
// ---------------------------------------------------------------------------
__device__ __forceinline__ unsigned fkey(float v) {
    unsigned u = __float_as_uint(v);
    return (u & 0x80000000u) ? ~u : (u | 0x80000000u);
}

struct SelShared { int T; int nsel; int neq; };

__device__ void suffix_scan(unsigned* h, int NB) {
    const int tid = threadIdx.x;
    for (int off = 1; off < NB; off <<= 1) {
        unsigned v[8];
        int c = 0;
        for (int idx = tid; idx < NB; idx += NTH) {
            const int srcIdx = idx + off;
            v[c++] = (srcIdx < NB) ? h[srcIdx] : 0u;
        }
        __syncthreads();
        c = 0;
        for (int idx = tid; idx < NB; idx += NTH) h[idx] += v[c++];
        __syncthreads();
    }
}

__device__ int find_T(unsigned* h, int NB, unsigned K, int* sT) {
    const int tid = threadIdx.x;
    for (int idx = tid; idx < NB; idx += NTH)
        if (h[idx] >= K && (idx == NB - 1 || h[idx + 1] < K)) *sT = idx;
    __syncthreads();
    return *sT;
}

// exact top-K of keys sk[0..F_) -> indices in selIdx[0..K)
__device__ void select_topk(const unsigned* sk, unsigned* hist,
                            int* selIdx, int* eqIdx, int K, SelShared* sh)
{
    const int tid = threadIdx.x;
    const unsigned Ku = (unsigned)K;

    // round 1: key bits [31:20]
    for (int i = tid; i < 4096; i += NTH) hist[i] = 0u;
    __syncthreads();
    for (int i = tid; i < F_; i += NTH) atomicAdd(&hist[sk[i] >> 20], 1u);
    __syncthreads();
    suffix_scan(hist, 4096);
    const int T1 = find_T(hist, 4096, Ku, &sh->T);
    const unsigned nA1 = (T1 < 4095) ? hist[T1 + 1] : 0u;
    unsigned Kr = Ku - nA1;
    __syncthreads();

    // round 2: bits [19:8], restricted to top12 == T1
    for (int i = tid; i < 4096; i += NTH) hist[i] = 0u;
    __syncthreads();
    for (int i = tid; i < F_; i += NTH) {
        const unsigned k = sk[i];
        if ((int)(k >> 20) == T1) atomicAdd(&hist[(k >> 8) & 0xFFFu], 1u);
    }
    __syncthreads();
    suffix_scan(hist, 4096);
    const int T2 = find_T(hist, 4096, Kr, &sh->T);
    const unsigned nA2 = (T2 < 4095) ? hist[T2 + 1] : 0u;
    Kr -= nA2;
    __syncthreads();

    // round 3: bits [7:0], restricted to top24 == (T1<<12)|T2
    const unsigned pre24 = ((unsigned)T1 << 12) | (unsigned)T2;
    for (int i = tid; i < 256; i += NTH) hist[i] = 0u;
    __syncthreads();
    for (int i = tid; i < F_; i += NTH) {
        const unsigned k = sk[i];
        if ((k >> 8) == pre24) atomicAdd(&hist[k & 0xFFu], 1u);
    }
    __syncthreads();
    suffix_scan(hist, 256);
    const int T3 = find_T(hist, 256, Kr, &sh->T);
    const unsigned nA3 = (T3 < 255) ? hist[T3 + 1] : 0u;
    const int needEq = (int)(Kr - nA3);
    const unsigned kth = (pre24 << 8) | (unsigned)T3;
    __syncthreads();

    // collect: all keys > kth, plus needEq keys == kth (lowest index first)
    if (tid == 0) { sh->nsel = 0; sh->neq = 0; }
    __syncthreads();
    for (int i = tid; i < F_; i += NTH) {
        const unsigned k = sk[i];
        if (k > kth) {
            const int p = atomicAdd(&sh->nsel, 1);
            selIdx[p] = i;
        } else if (k == kth) {
            const int p = atomicAdd(&sh->neq, 1);
            if (p < 64) eqIdx[p] = i;
        }
    }
    __syncthreads();
    if (tid == 0) {
        int m = sh->neq; if (m > 64) m = 64;
        for (int a = 1; a < m; a++) {           // tiny insertion sort by index
            int v = eqIdx[a]; int c = a - 1;
            while (c >= 0 && eqIdx[c] > v) { eqIdx[c + 1] = eqIdx[c]; c--; }
            eqIdx[c + 1] = v;
        }
        const int base = sh->nsel;
        for (int a = 0; a < needEq; a++)
            selIdx[base + a] = (a < m) ? eqIdx[a] : eqIdx[0];
    }
    __syncthreads();
}

__global__ __launch_bounds__(NTH)
void row_kernel(const float* __restrict__ noise,
                const int*   __restrict__ last_usage,
                const float* __restrict__ lookup,
                const float* __restrict__ bias,
                float* __restrict__ out)
{
    extern __shared__ unsigned char smem_raw[];
    float*    sp     = (float*)smem_raw;                                  // F_
    unsigned* sk     = (unsigned*)(smem_raw + (size_t)F_ * 4);            // F_
    unsigned* hist   = (unsigned*)(smem_raw + (size_t)F_ * 8);            // 4096
    int*      selIdx = (int*)(smem_raw + (size_t)F_ * 8 + 4096 * 4);      // 256
    int*      eqIdx  = (int*)((char*)selIdx + 256 * 4);                   // 64

    __shared__ SelShared sh;
    __shared__ int   feats32[K1];
    __shared__ float w32[K1];
    __shared__ float uw[K2_];

    const int tid = threadIdx.x;
    const int b   = blockIdx.x;

    // load this row of project into smem
    const float* prow = g_project + (size_t)b * F_;
    for (int i = tid; i < F_; i += NTH) sp[i] = prow[i];

    // fuzz = std(project, ddof=1) * FUZZ_FACTOR(=1)
    const double S  = g_sum;
    const double SS = g_sumsq;
    const double N  = (double)B_ * (double)F_;
    const float fuzz = (float)sqrt((SS - S * S / N) / (N - 1.0));

    // ---- pass 1: top-32 of project ----
    __syncthreads();
    for (int i = tid; i < F_; i += NTH) sk[i] = fkey(sp[i]);
    __syncthreads();
    select_topk(sk, hist, selIdx, eqIdx, K1, &sh);
    for (int j = tid; j < K1; j += NTH) {
        feats32[j] = selIdx[j];
        w32[j]     = sp[selIdx[j]];
    }
    __syncthreads();

    // ---- pass 2: top-256 of fuzzed dead features ----
    const float* nrow = noise + (size_t)b * F_;
    for (int i = tid; i < F_; i += NTH)
        sk[i] = (last_usage[i] > DEAD_CUT) ? fkey(sp[i] + fuzz * nrow[i]) : 0u;
    __syncthreads();
    select_topk(sk, hist, selIdx, eqIdx, K2_, &sh);
    for (int j = tid; j < K2_; j += NTH) uw[j] = sp[selIdx[j]];   // weight = project value
    __syncthreads();

    // ---- reconstruction ----
    for (int d = tid; d < D_; d += NTH) {
        float a = bias[d];
#pragma unroll 8
        for (int k = 0; k < K1; k++)
            a += w32[k] * lookup[(size_t)feats32[k] * D_ + d];
        out[(size_t)b * D_ + d] = a;

        float a0 = 0.f, a1 = 0.f, a2 = 0.f, a3 = 0.f;
#pragma unroll 2
        for (int k = 0; k < K2_; k += 4) {
            a0 += uw[k + 0] * lookup[(size_t)selIdx[k + 0] * D_ + d];
            a1 += uw[k + 1] * lookup[(size_t)selIdx[k + 1] * D_ + d];
            a2 += uw[k + 2] * lookup[(size_t)selIdx[k + 2] * D_ + d];
            a3 += uw[k + 3] * lookup[(size_t)selIdx[k + 3] * D_ + d];
        }
        out[(size_t)B_ * D_ + (size_t)b * D_ + d] = (a0 + a1) + (a2 + a3);
    }
}

// ---------------------------------------------------------------------------
// Launch
// ---------------------------------------------------------------------------
extern "C" void kernel_launch(void* const* d_in, const int* in_sizes, int n_in,
                              void* d_out, int out_size)
{
    (void)in_sizes; (void)n_in; (void)out_size;
    const float* embed      = (const float*)d_in[0];
    const float* enc_bias   = (const float*)d_in[1];
    const float* enc_W      = (const float*)d_in[2];
    const float* lookup     = (const float*)d_in[3];
    const float* noise      = (const float*)d_in[4];
    const int*   last_usage = (const int*)  d_in[5];
    float* out = (float*)d_out;

    const size_t smem_bytes = (size_t)F_ * 8 + 4096 * 4 + 256 * 4 + 64 * 4; // 214272
    cudaFuncSetAttribute(row_kernel,
                         cudaFuncAttributeMaxDynamicSharedMemorySize,
                         (int)smem_bytes);

    gemm_kernel<<<dim3(GRID_X, GRID_Y), 256>>>(embed, enc_bias, enc_W);
    reduce_stats_kernel<<<1, 512>>>();
    row_kernel<<<B_, NTH, smem_bytes>>>(noise, last_usage, lookup, enc_bias, out);
}

// round 14
// speedup vs baseline: 2.1765x; 1.0524x over previous
#include <cuda_runtime.h>
#include <math.h>

#define B_   4096
#define D_   1024
#define F_   24576
#define K1   32      /* TOPK */
#define K2_  256     /* DEAD_TOPK */
#define DEAD_CUT 100000
#define NTH  512     /* threads in row kernel */

#define GRID_X (F_ / 128)
#define GRID_Y (B_ / 128)
#define NBLK   (GRID_X * GRID_Y)

// ---------------------------------------------------------------------------
// Scratch (device globals: no cudaMalloc allowed)
// ---------------------------------------------------------------------------
__device__ float  g_project[(size_t)B_ * (size_t)F_];   // 402 MB
__device__ double g_part[NBLK][2];                      // per-CTA (sum, sumsq)
__device__ double g_sum;
__device__ double g_sumsq;

// Deterministic reduction of per-CTA partials -> g_sum / g_sumsq.
__global__ __launch_bounds__(512)
void reduce_stats_kernel() {
    const int tid = threadIdx.x;
    double s = 0.0, ss = 0.0;
    for (int i = tid; i < NBLK; i += 512) {
        s  += g_part[i][0];
        ss += g_part[i][1];
    }
    __shared__ double sh_s[512], sh_ss[512];
    sh_s[tid] = s; sh_ss[tid] = ss;
    __syncthreads();
    for (int off = 256; off > 0; off >>= 1) {
        if (tid < off) {
            sh_s[tid]  += sh_s[tid + off];
            sh_ss[tid] += sh_ss[tid + off];
        }
        __syncthreads();
    }
    if (tid == 0) { g_sum = sh_s[0]; g_sumsq = sh_ss[0]; }
}

// ---------------------------------------------------------------------------
// packed f32x2 helpers (SASS FFMA2). Each half is an IEEE fp32 FMA.
// ---------------------------------------------------------------------------
__device__ __forceinline__ void fma2(unsigned long long& d,
                                     unsigned long long a,
                                     unsigned long long b) {
    asm("fma.rn.f32x2 %0, %1, %2, %0;" : "+l"(d) : "l"(a), "l"(b));
}
__device__ __forceinline__ void add2(unsigned long long& d,
                                     unsigned long long a) {
    asm("add.rn.f32x2 %0, %0, %1;" : "+l"(d) : "l"(a));
}
__device__ __forceinline__ unsigned long long dupf(float x) {
    unsigned long long r;
    asm("mov.b64 %0, {%1, %1};" : "=l"(r) : "f"(x));
    return r;
}
__device__ __forceinline__ void unpack2(unsigned long long v, float& lo, float& hi) {
    asm("mov.b64 {%0, %1}, %2;" : "=f"(lo), "=f"(hi) : "l"(v));
}

// XOR swizzle of 16-byte chunks within a 128-float Bs row (as in R13):
// chunk q -> q ^ ((q>>3)&1). Conflict-free for the 32-B-stride fragment loads.
__device__ __forceinline__ int bswiz(int c) {
    int q = c >> 2;
    q ^= (q >> 3) & 1;
    return (q << 2) | (c & 3);
}

// ---------------------------------------------------------------------------
// SGEMM: project[b,f] = sum_d (embed[b,d]-bias[d]) * W[f,d]
// 128x128 tile, BK=16, now 512 threads, 4x8 micro-tile (2 row-pairs x 8 cols),
// smem double buffered, FFMA2 mainloop, swizzled Bs.
// Element redistribution only: per-element FP op sequence identical to R13
// (same kk order, same BK=16 two-level fold) -> bit-exact GEMM results.
// 512 threads => 16 warps/SM (4 per SMSP) for latency hiding; regs ~120.
// ---------------------------------------------------------------------------
#define BM 128
#define BN 128
#define BK 16

__global__ __launch_bounds__(512, 1)
void gemm_kernel(const float* __restrict__ embed,
                 const float* __restrict__ bias,
                 const float* __restrict__ W)
{
    __shared__ __align__(16) float As[2][BK][BM];
    __shared__ __align__(16) float Bs[2][BK][BN];

    const int tid  = threadIdx.x;
    const int row0 = blockIdx.y * BM;   // batch rows
    const int col0 = blockIdx.x * BN;   // feature cols

    // loader mapping: each of 512 threads loads ONE float4 of A and of B
    const int ar = tid >> 2;                  // rows 0..127
    const int aq = tid & 3;                   // which float4 of the 16-wide k slab
    const int brs = bswiz(ar);                // swizzled B store column

    const float* Ap = embed + (size_t)(row0 + ar) * D_ + aq * 4;
    const float* Bp = W     + (size_t)(col0 + ar) * D_ + aq * 4;

    // paired accumulators: acc2[p][j] = rows (ty*4+2p, ty*4+2p+1), col tx*8+j
    unsigned long long acc2[2][8];
#pragma unroll
    for (int p = 0; p < 2; p++)
#pragma unroll
        for (int j = 0; j < 8; j++) acc2[p][j] = 0ull;

    float4 a0, b0, bb;

    // preload tile 0
    a0 = *(const float4*)(Ap);
    b0 = *(const float4*)(Bp);
    bb = *(const float4*)(bias + aq * 4);

    int buf = 0;
    {
        const int kc = aq * 4;
        As[0][kc+0][ar] = a0.x - bb.x;  As[0][kc+1][ar] = a0.y - bb.y;
        As[0][kc+2][ar] = a0.z - bb.z;  As[0][kc+3][ar] = a0.w - bb.w;
        Bs[0][kc+0][brs] = b0.x;  Bs[0][kc+1][brs] = b0.y;
        Bs[0][kc+2][brs] = b0.z;  Bs[0][kc+3][brs] = b0.w;
    }
    __syncthreads();

    const int ty = tid >> 4;   // 0..31  -> rows ty*4 .. ty*4+3
    const int tx = tid & 15;   // 0..15  -> cols tx*8 .. tx*8+7
    const int NT = D_ / BK;    // 64

    // swizzled load columns for the two B fragments (16-B aligned chunks)
    const int txs0 = bswiz(tx * 8);
    const int txs1 = bswiz(tx * 8 + 4);

    for (int t = 0; t < NT; t++) {
        if (t + 1 < NT) {
            const int k0 = (t + 1) * BK;
            a0 = *(const float4*)(Ap + k0);
            b0 = *(const float4*)(Bp + k0);
            bb = *(const float4*)(bias + k0 + aq * 4);
        }
        // per-tile partial sums (fresh registers -> short rounding chains)
        unsigned long long ts2[2][8];
#pragma unroll
        for (int p = 0; p < 2; p++)
#pragma unroll
            for (int j = 0; j < 8; j++) ts2[p][j] = 0ull;

#pragma unroll
        for (int kk = 0; kk < BK; kk++) {
            // A: one LDS.128 = rows ty*4..ty*4+3 = 2 pairs
            ulonglong2 pa = *(const ulonglong2*)&As[buf][kk][ty * 4];
            // B: two LDS.128 (swizzled, conflict-free), duplicate in registers
            float4 f0 = *(const float4*)&Bs[buf][kk][txs0];
            float4 f1 = *(const float4*)&Bs[buf][kk][txs1];
            unsigned long long b2[8] = {
                dupf(f0.x), dupf(f0.y), dupf(f0.z), dupf(f0.w),
                dupf(f1.x), dupf(f1.y), dupf(f1.z), dupf(f1.w)
            };
#pragma unroll
            for (int j = 0; j < 8; j++) fma2(ts2[0][j], pa.x, b2[j]);
#pragma unroll
            for (int j = 0; j < 8; j++) fma2(ts2[1][j], pa.y, b2[j]);
        }
#pragma unroll
        for (int p = 0; p < 2; p++)
#pragma unroll
            for (int j = 0; j < 8; j++)
                add2(acc2[p][j], ts2[p][j]);

        if (t + 1 < NT) {
            const int nb = buf ^ 1;
            const int kc = aq * 4;
            As[nb][kc+0][ar] = a0.x - bb.x;  As[nb][kc+1][ar] = a0.y - bb.y;
            As[nb][kc+2][ar] = a0.z - bb.z;  As[nb][kc+3][ar] = a0.w - bb.w;
            Bs[nb][kc+0][brs] = b0.x;  Bs[nb][kc+1][brs] = b0.y;
            Bs[nb][kc+2][brs] = b0.z;  Bs[nb][kc+3][brs] = b0.w;
            __syncthreads();
            buf = nb;
        }
    }

    // unpack pairs to scalars: rows ty*4 + 2p + {0,1}
    float acc[4][8];
#pragma unroll
    for (int p = 0; p < 2; p++)
#pragma unroll
        for (int j = 0; j < 8; j++)
            unpack2(acc2[p][j], acc[2*p][j], acc[2*p+1][j]);

    // write C + accumulate stats
    float s = 0.0f, ss = 0.0f;
#pragma unroll
    for (int i = 0; i < 4; i++) {
        const size_t base = (size_t)(row0 + ty * 4 + i) * F_ + (col0 + tx * 8);
        float4 c0 = make_float4(acc[i][0], acc[i][1], acc[i][2], acc[i][3]);
        float4 c1 = make_float4(acc[i][4], acc[i][5], acc[i][6], acc[i][7]);
        *(float4*)&g_project[base]     = c0;
        *(float4*)&g_project[base + 4] = c1;
#pragma unroll
        for (int j = 0; j < 8; j++) { float v = acc[i][j]; s += v; ss += v * v; }
    }
#pragma unroll
    for (int o = 16; o > 0; o >>= 1) {
        s  += __shfl_down_sync(0xffffffffu, s,  o);
        ss += __shfl_down_sync(0xffffffffu, ss, o);
    }
    __shared__ double wsum[16], wss[16];
    const int w = tid >> 5, l = tid & 31;
    if (l == 0) { wsum[w] = (double)s; wss[w] = (double)ss; }
    __syncthreads();
    if (tid == 0) {
        double S = 0.0, SS = 0.0;
        for (int i = 0; i < 16; i++) { S += wsum[i]; SS += wss[i]; }
        const int bid = blockIdx.y * gridDim.x + blockIdx.x;
        g_part[bid][0] = S;
        g_part[bid][1] = SS;
    }
}

// ---------------------------------------------------------------------------
// Per-row top-k (exact radix select on monotone float keys) + reconstruction
// ---------------------------------------------------------------------------
__device__ __forceinline__ unsigned fkey(float v) {
    unsigned u = __float_as_uint(v);
    return (u & 0x80000000u) ? ~u : (u | 0x80000000u);
}

struct SelShared { int T; int nsel; int neq; };

__device__ void suffix_scan(unsigned* h, int NB) {
    const int tid = threadIdx.x;
    for (int off = 1; off < NB; off <<= 1) {
        unsigned v[8];
        int c = 0;
        for (int idx = tid; idx < NB; idx += NTH) {
            const int srcIdx = idx + off;
            v[c++] = (srcIdx < NB) ? h[srcIdx] : 0u;
        }
        __syncthreads();
        c = 0;
        for (int idx = tid; idx < NB; idx += NTH) h[idx] += v[c++];
        __syncthreads();
    }
}

__device__ int find_T(unsigned* h, int NB, unsigned K, int* sT) {
    const int tid = threadIdx.x;
    for (int idx = tid; idx < NB; idx += NTH)
        if (h[idx] >= K && (idx == NB - 1 || h[idx + 1] < K)) *sT = idx;
    __syncthreads();
    return *sT;
}

// exact top-K of keys sk[0..F_) -> indices in selIdx[0..K)
__device__ void select_topk(const unsigned* sk, unsigned* hist,
                            int* selIdx, int* eqIdx, int K, SelShared* sh)
{
    const int tid = threadIdx.x;
    const unsigned Ku = (unsigned)K;

    // round 1: key bits [31:20]
    for (int i = tid; i < 4096; i += NTH) hist[i] = 0u;
    __syncthreads();
    for (int i = tid; i < F_; i += NTH) atomicAdd(&hist[sk[i] >> 20], 1u);
    __syncthreads();
    suffix_scan(hist, 4096);
    const int T1 = find_T(hist, 4096, Ku, &sh->T);
    const unsigned nA1 = (T1 < 4095) ? hist[T1 + 1] : 0u;
    unsigned Kr = Ku - nA1;
    __syncthreads();

    // round 2: bits [19:8], restricted to top12 == T1
    for (int i = tid; i < 4096; i += NTH) hist[i] = 0u;
    __syncthreads();
    for (int i = tid; i < F_; i += NTH) {
        const unsigned k = sk[i];
        if ((int)(k >> 20) == T1) atomicAdd(&hist[(k >> 8) & 0xFFFu], 1u);
    }
    __syncthreads();
    suffix_scan(hist, 4096);
    const int T2 = find_T(hist, 4096, Kr, &sh->T);
    const unsigned nA2 = (T2 < 4095) ? hist[T2 + 1] : 0u;
    Kr -= nA2;
    __syncthreads();

    // round 3: bits [7:0], restricted to top24 == (T1<<12)|T2
    const unsigned pre24 = ((unsigned)T1 << 12) | (unsigned)T2;
    for (int i = tid; i < 256; i += NTH) hist[i] = 0u;
    __syncthreads();
    for (int i = tid; i < F_; i += NTH) {
        const unsigned k = sk[i];
        if ((k >> 8) == pre24) atomicAdd(&hist[k & 0xFFu], 1u);
    }
    __syncthreads();
    suffix_scan(hist, 256);
    const int T3 = find_T(hist, 256, Kr, &sh->T);
    const unsigned nA3 = (T3 < 255) ? hist[T3 + 1] : 0u;
    const int needEq = (int)(Kr - nA3);
    const unsigned kth = (pre24 << 8) | (unsigned)T3;
    __syncthreads();

    // collect: all keys > kth, plus needEq keys == kth (lowest index first)
    if (tid == 0) { sh->nsel = 0; sh->neq = 0; }
    __syncthreads();
    for (int i = tid; i < F_; i += NTH) {
        const unsigned k = sk[i];
        if (k > kth) {
            const int p = atomicAdd(&sh->nsel, 1);
            selIdx[p] = i;
        } else if (k == kth) {
            const int p = atomicAdd(&sh->neq, 1);
            if (p < 64) eqIdx[p] = i;
        }
    }
    __syncthreads();
    if (tid == 0) {
        int m = sh->neq; if (m > 64) m = 64;
        for (int a = 1; a < m; a++) {           // tiny insertion sort by index
            int v = eqIdx[a]; int c = a - 1;
            while (c >= 0 && eqIdx[c] > v) { eqIdx[c + 1] = eqIdx[c]; c--; }
            eqIdx[c + 1] = v;
        }
        const int base = sh->nsel;
        for (int a = 0; a < needEq; a++)
            selIdx[base + a] = (a < m) ? eqIdx[a] : eqIdx[0];
    }
    __syncthreads();
}

__global__ __launch_bounds__(NTH)
void row_kernel(const float* __restrict__ noise,
                const int*   __restrict__ last_usage,
                const float* __restrict__ lookup,
                const float* __restrict__ bias,
                float* __restrict__ out)
{
    extern __shared__ unsigned char smem_raw[];
    float*    sp     = (float*)smem_raw;                                  // F_
    unsigned* sk     = (unsigned*)(smem_raw + (size_t)F_ * 4);            // F_
    unsigned* hist   = (unsigned*)(smem_raw + (size_t)F_ * 8);            // 4096
    int*      selIdx = (int*)(smem_raw + (size_t)F_ * 8 + 4096 * 4);      // 256
    int*      eqIdx  = (int*)((char*)selIdx + 256 * 4);                   // 64

    __shared__ SelShared sh;
    __shared__ int   feats32[K1];
    __shared__ float w32[K1];
    __shared__ float uw[K2_];

    const int tid = threadIdx.x;
    const int b   = blockIdx.x;

    // load this row of project into smem
    const float* prow = g_project + (size_t)b * F_;
    for (int i = tid; i < F_; i += NTH) sp[i] = prow[i];

    // fuzz = std(project, ddof=1) * FUZZ_FACTOR(=1)
    const double S  = g_sum;
    const double SS = g_sumsq;
    const double N  = (double)B_ * (double)F_;
    const float fuzz = (float)sqrt((SS - S * S / N) / (N - 1.0));

    // ---- pass 1: top-32 of project ----
    __syncthreads();
    for (int i = tid; i < F_; i += NTH) sk[i] = fkey(sp[i]);
    __syncthreads();
    select_topk(sk, hist, selIdx, eqIdx, K1, &sh);
    for (int j = tid; j < K1; j += NTH) {
        feats32[j] = selIdx[j];
        w32[j]     = sp[selIdx[j]];
    }
    __syncthreads();

    // ---- pass 2: top-256 of fuzzed dead features ----
    const float* nrow = noise + (size_t)b * F_;
    for (int i = tid; i < F_; i += NTH)
        sk[i] = (last_usage[i] > DEAD_CUT) ? fkey(sp[i] + fuzz * nrow[i]) : 0u;
    __syncthreads();
    select_topk(sk, hist, selIdx, eqIdx, K2_, &sh);
    for (int j = tid; j < K2_; j += NTH) uw[j] = sp[selIdx[j]];   // weight = project value
    __syncthreads();

    // ---- reconstruction ----
    for (int d = tid; d < D_; d += NTH) {
        float a = bias[d];
#pragma unroll 8
        for (int k = 0; k < K1; k++)
            a += w32[k] * lookup[(size_t)feats32[k] * D_ + d];
        out[(size_t)b * D_ + d] = a;

        float a0 = 0.f, a1 = 0.f, a2 = 0.f, a3 = 0.f;
#pragma unroll 2
        for (int k = 0; k < K2_; k += 4) {
            a0 += uw[k + 0] * lookup[(size_t)selIdx[k + 0] * D_ + d];
            a1 += uw[k + 1] * lookup[(size_t)selIdx[k + 1] * D_ + d];
            a2 += uw[k + 2] * lookup[(size_t)selIdx[k + 2] * D_ + d];
            a3 += uw[k + 3] * lookup[(size_t)selIdx[k + 3] * D_ + d];
        }
        out[(size_t)B_ * D_ + (size_t)b * D_ + d] = (a0 + a1) + (a2 + a3);
    }
}

// ---------------------------------------------------------------------------
// Launch
// ---------------------------------------------------------------------------
extern "C" void kernel_launch(void* const* d_in, const int* in_sizes, int n_in,
                              void* d_out, int out_size)
{
    (void)in_sizes; (void)n_in; (void)out_size;
    const float* embed      = (const float*)d_in[0];
    const float* enc_bias   = (const float*)d_in[1];
    const float* enc_W      = (const float*)d_in[2];
    const float* lookup     = (const float*)d_in[3];
    const float* noise      = (const float*)d_in[4];
    const int*   last_usage = (const int*)  d_in[5];
    float* out = (float*)d_out;

    const size_t smem_bytes = (size_t)F_ * 8 + 4096 * 4 + 256 * 4 + 64 * 4; // 214272
    cudaFuncSetAttribute(row_kernel,
                         cudaFuncAttributeMaxDynamicSharedMemorySize,
                         (int)smem_bytes);

    gemm_kernel<<<dim3(GRID_X, GRID_Y), 512>>>(embed, enc_bias, enc_W);
    reduce_stats_kernel<<<1, 512>>>();
    row_kernel<<<B_, NTH, smem_bytes>>>(noise, last_usage, lookup, enc_bias, out);
}